// round 2
// baseline (speedup 1.0000x reference)
#include <cuda_runtime.h>
#include <cstdint>
#include <cstdio>

#define NTOK 8192
#define DIN  512
#define DHEAD 256
#define NSPLIT 4
#define BM 128
#define BN 64
#define KEYS_PER_SPLIT (NTOK / NSPLIT)

// ---------------- scratch (static device globals; no allocation) ----------------
__device__ float g_Q[NTOK * DHEAD];
__device__ float g_K[NTOK * DHEAD];
__device__ float g_V[NTOK * DHEAD];
__device__ float g_Op[NSPLIT][NTOK][DHEAD];
__device__ float g_ms[NSPLIT][NTOK];
__device__ float g_ls[NSPLIT][NTOK];

// ---------------- helpers ----------------
__device__ __forceinline__ unsigned tf32_rna_u(float x) {
    unsigned u;
    asm("cvt.rna.tf32.f32 %0, %1;" : "=r"(u) : "f"(x));
    return u;
}
__device__ __forceinline__ float tf32_rna(float x) { return __uint_as_float(tf32_rna_u(x)); }

__device__ __forceinline__ void mma_tf32(float& c0, float& c1, float& c2, float& c3,
                                         unsigned a0, unsigned a1, unsigned a2, unsigned a3,
                                         unsigned b0, unsigned b1) {
    asm volatile(
        "mma.sync.aligned.m16n8k8.row.col.f32.tf32.tf32.f32 "
        "{%0,%1,%2,%3}, {%4,%5,%6,%7}, {%8,%9}, {%0,%1,%2,%3};"
        : "+f"(c0), "+f"(c1), "+f"(c2), "+f"(c3)
        : "r"(a0), "r"(a1), "r"(a2), "r"(a3), "r"(b0), "r"(b1));
}

// ---------------- kernel 1: QKV projection, tf32 x2 (split-A) ----------------
// C[8192,256] = feat[8192,512] @ W[512,256], for W in {Wq,Wk,Wv}.
// Q is pre-scaled by 1/16 (exact) and all outputs are tf32-rounded on store.
__global__ __launch_bounds__(256) void proj_kernel(const float* __restrict__ feat,
                                                   const float* __restrict__ Wq,
                                                   const float* __restrict__ Wk,
                                                   const float* __restrict__ Wv) {
    __shared__ float As[2][128][20];   // [hi/lo][row][k], stride 20 -> conflict-free frags
    __shared__ float Bs[16][136];      // [k][col], stride 136 -> conflict-free frags

    const int tid = threadIdx.x;
    const int w = tid >> 5, lane = tid & 31, g = lane >> 2, t = lane & 3;
    const int wm = w >> 1, wn = w & 1;
    const int m0 = blockIdx.x * 128;
    const int n0 = blockIdx.y * 128;
    const int mat = blockIdx.z;
    const float* __restrict__ W = (mat == 0) ? Wq : ((mat == 1) ? Wk : Wv);

    float acc[2][8][4];
#pragma unroll
    for (int mt = 0; mt < 2; mt++)
#pragma unroll
        for (int nt = 0; nt < 8; nt++)
#pragma unroll
            for (int j = 0; j < 4; j++) acc[mt][nt][j] = 0.f;

    for (int kb = 0; kb < DIN; kb += 16) {
        // load A tile [128][16], split into hi/lo tf32
#pragma unroll
        for (int i = 0; i < 2; i++) {
            int e = tid + 256 * i;
            int r = e >> 2, c = (e & 3) << 2;
            float4 v = *(const float4*)&feat[(size_t)(m0 + r) * DIN + kb + c];
            float h;
            h = tf32_rna(v.x); As[0][r][c + 0] = h; As[1][r][c + 0] = tf32_rna(v.x - h);
            h = tf32_rna(v.y); As[0][r][c + 1] = h; As[1][r][c + 1] = tf32_rna(v.y - h);
            h = tf32_rna(v.z); As[0][r][c + 2] = h; As[1][r][c + 2] = tf32_rna(v.z - h);
            h = tf32_rna(v.w); As[0][r][c + 3] = h; As[1][r][c + 3] = tf32_rna(v.w - h);
        }
        // load B tile [16][128]
#pragma unroll
        for (int i = 0; i < 2; i++) {
            int e = tid + 256 * i;
            int r = e >> 5, c = (e & 31) << 2;
            float4 v = *(const float4*)&W[(size_t)(kb + r) * DHEAD + n0 + c];
            Bs[r][c + 0] = tf32_rna(v.x);
            Bs[r][c + 1] = tf32_rna(v.y);
            Bs[r][c + 2] = tf32_rna(v.z);
            Bs[r][c + 3] = tf32_rna(v.w);
        }
        __syncthreads();

#pragma unroll
        for (int ks = 0; ks < 16; ks += 8) {
            unsigned b[8][2];
#pragma unroll
            for (int nt = 0; nt < 8; nt++) {
                int col = 64 * wn + 8 * nt + g;
                b[nt][0] = __float_as_uint(Bs[ks + t][col]);
                b[nt][1] = __float_as_uint(Bs[ks + t + 4][col]);
            }
#pragma unroll
            for (int sp2 = 0; sp2 < 2; sp2++) {
#pragma unroll
                for (int mt = 0; mt < 2; mt++) {
                    int r = 32 * wm + 16 * mt + g;
                    unsigned a0 = __float_as_uint(As[sp2][r][ks + t]);
                    unsigned a1 = __float_as_uint(As[sp2][r + 8][ks + t]);
                    unsigned a2 = __float_as_uint(As[sp2][r][ks + t + 4]);
                    unsigned a3 = __float_as_uint(As[sp2][r + 8][ks + t + 4]);
#pragma unroll
                    for (int nt = 0; nt < 8; nt++)
                        mma_tf32(acc[mt][nt][0], acc[mt][nt][1], acc[mt][nt][2], acc[mt][nt][3],
                                 a0, a1, a2, a3, b[nt][0], b[nt][1]);
                }
            }
        }
        __syncthreads();
    }

    const float scale = (mat == 0) ? 0.0625f : 1.0f;  // fold 1/sqrt(256) into Q
    float* __restrict__ dst = (mat == 0) ? g_Q : ((mat == 1) ? g_K : g_V);
#pragma unroll
    for (int mt = 0; mt < 2; mt++) {
        int r = m0 + 32 * wm + 16 * mt + g;
#pragma unroll
        for (int nt = 0; nt < 8; nt++) {
            int col = n0 + 64 * wn + 8 * nt + 2 * t;
            float2 v0 = make_float2(tf32_rna(acc[mt][nt][0] * scale), tf32_rna(acc[mt][nt][1] * scale));
            float2 v1 = make_float2(tf32_rna(acc[mt][nt][2] * scale), tf32_rna(acc[mt][nt][3] * scale));
            *(float2*)&dst[(size_t)r * DHEAD + col] = v0;
            *(float2*)&dst[(size_t)(r + 8) * DHEAD + col] = v1;
        }
    }
}

// ---------------- kernel 2: fused flash attention (split-K over keys) ----------------
// Per CTA: 128 query rows x 2048 keys (split sp). Online softmax with counting mask.
__global__ __launch_bounds__(256, 1) void attn_kernel(const float* __restrict__ cnt) {
    extern __shared__ float smem_f[];
    float* Qs = smem_f;                       // [128][256], xor-swizzled
    float* KVs = smem_f + 128 * 256;          // [64][256], K then V
    float* Cs = KVs + 64 * 256;               // [128][64], counting then P

    const int tid = threadIdx.x;
    const int w = tid >> 5, lane = tid & 31, g = lane >> 2, t = lane & 3;
    const int m0 = blockIdx.x * BM;
    const int sp = blockIdx.y;
    const int rowA = 16 * w + g;  // this warp's two row ids within tile
    const int rowB = rowA + 8;

    // load Q tile (already tf32-rounded + 1/16 scaled)
#pragma unroll
    for (int i = 0; i < 32; i++) {
        int e = tid + 256 * i;
        int r = e >> 6, c = (e & 63) << 2;
        float4 v = *(const float4*)&g_Q[(size_t)(m0 + r) * DHEAD + c];
        *(float4*)&Qs[r * 256 + (c ^ ((r & 7) << 2))] = v;
    }

    float O[32][4];
#pragma unroll
    for (int nt = 0; nt < 32; nt++)
#pragma unroll
        for (int j = 0; j < 4; j++) O[nt][j] = 0.f;
    float m0r = -1e30f, m1r = -1e30f, l0r = 0.f, l1r = 0.f;

    const int jb_begin = sp * KEYS_PER_SPLIT;
    for (int jb = jb_begin; jb < jb_begin + KEYS_PER_SPLIT; jb += BN) {
        __syncthreads();  // prior-iter AV reads of KVs/Cs complete
        // load K block [64][256]
#pragma unroll
        for (int i = 0; i < 16; i++) {
            int e = tid + 256 * i;
            int r = e >> 6, c = (e & 63) << 2;
            float4 v = *(const float4*)&g_K[(size_t)(jb + r) * DHEAD + c];
            *(float4*)&KVs[r * 256 + (c ^ ((r & 7) << 2))] = v;
        }
        // load counting tile [128][64]
#pragma unroll
        for (int i = 0; i < 8; i++) {
            int e = tid + 256 * i;
            int r = e >> 4, c = (e & 15) << 2;
            float4 v = *(const float4*)&cnt[(size_t)(m0 + r) * NTOK + jb + c];
            *(float4*)&Cs[r * 64 + (c ^ ((r & 7) << 2))] = v;
        }
        __syncthreads();

        // S = Q K^T (scale folded into Q): warp computes [16 x 64]
        float S[8][4];
#pragma unroll
        for (int nt = 0; nt < 8; nt++)
#pragma unroll
            for (int j = 0; j < 4; j++) S[nt][j] = 0.f;

#pragma unroll 4
        for (int s = 0; s < 32; s++) {
            int k0 = 8 * s;
            unsigned a0 = __float_as_uint(Qs[rowA * 256 + ((k0 + t) ^ (g << 2))]);
            unsigned a1 = __float_as_uint(Qs[rowB * 256 + ((k0 + t) ^ (g << 2))]);
            unsigned a2 = __float_as_uint(Qs[rowA * 256 + ((k0 + t + 4) ^ (g << 2))]);
            unsigned a3 = __float_as_uint(Qs[rowB * 256 + ((k0 + t + 4) ^ (g << 2))]);
#pragma unroll
            for (int nt = 0; nt < 8; nt++) {
                int n = 8 * nt + g;
                unsigned b0 = __float_as_uint(KVs[n * 256 + ((k0 + t) ^ (g << 2))]);
                unsigned b1 = __float_as_uint(KVs[n * 256 + ((k0 + t + 4) ^ (g << 2))]);
                mma_tf32(S[nt][0], S[nt][1], S[nt][2], S[nt][3], a0, a1, a2, a3, b0, b1);
            }
        }

        // online softmax: row max over this key block
        float bm0 = -1e30f, bm1 = -1e30f;
#pragma unroll
        for (int nt = 0; nt < 8; nt++) {
            bm0 = fmaxf(bm0, fmaxf(S[nt][0], S[nt][1]));
            bm1 = fmaxf(bm1, fmaxf(S[nt][2], S[nt][3]));
        }
        bm0 = fmaxf(bm0, __shfl_xor_sync(0xffffffffu, bm0, 1));
        bm0 = fmaxf(bm0, __shfl_xor_sync(0xffffffffu, bm0, 2));
        bm1 = fmaxf(bm1, __shfl_xor_sync(0xffffffffu, bm1, 1));
        bm1 = fmaxf(bm1, __shfl_xor_sync(0xffffffffu, bm1, 2));
        float mn0 = fmaxf(m0r, bm0), mn1 = fmaxf(m1r, bm1);
        float al0 = __expf(m0r - mn0), al1 = __expf(m1r - mn1);
        m0r = mn0; m1r = mn1;

        // P = exp(S - m) * counting; store P (tf32) back into Cs; row sums
        float s0 = 0.f, s1 = 0.f;
#pragma unroll
        for (int nt = 0; nt < 8; nt++) {
            int col = (8 * nt + 2 * t) ^ (g << 2);
            float2 cA = *(float2*)&Cs[rowA * 64 + col];
            float2 cB = *(float2*)&Cs[rowB * 64 + col];
            float p0 = __expf(S[nt][0] - mn0) * cA.x;
            float p1 = __expf(S[nt][1] - mn0) * cA.y;
            float p2 = __expf(S[nt][2] - mn1) * cB.x;
            float p3 = __expf(S[nt][3] - mn1) * cB.y;
            s0 += p0 + p1;
            s1 += p2 + p3;
            *(float2*)&Cs[rowA * 64 + col] = make_float2(tf32_rna(p0), tf32_rna(p1));
            *(float2*)&Cs[rowB * 64 + col] = make_float2(tf32_rna(p2), tf32_rna(p3));
        }
        s0 += __shfl_xor_sync(0xffffffffu, s0, 1);
        s0 += __shfl_xor_sync(0xffffffffu, s0, 2);
        s1 += __shfl_xor_sync(0xffffffffu, s1, 1);
        s1 += __shfl_xor_sync(0xffffffffu, s1, 2);
        l0r = l0r * al0 + s0;
        l1r = l1r * al1 + s1;

        // rescale O accumulators
#pragma unroll
        for (int nt = 0; nt < 32; nt++) {
            O[nt][0] *= al0; O[nt][1] *= al0;
            O[nt][2] *= al1; O[nt][3] *= al1;
        }
        __syncthreads();  // P visible to all warps; K reads done -> safe to overwrite with V

        // load V block [64][256] (already tf32-rounded), V-specific swizzle
#pragma unroll
        for (int i = 0; i < 16; i++) {
            int e = tid + 256 * i;
            int r = e >> 6, c = (e & 63) << 2;
            float4 v = *(const float4*)&g_V[(size_t)(jb + r) * DHEAD + c];
            *(float4*)&KVs[r * 256 + (c ^ ((r & 3) << 3))] = v;
        }
        __syncthreads();

        // O += P @ V : warp [16 x 256]
#pragma unroll
        for (int s = 0; s < 8; s++) {
            unsigned a0 = __float_as_uint(Cs[rowA * 64 + ((8 * s + t) ^ (g << 2))]);
            unsigned a1 = __float_as_uint(Cs[rowB * 64 + ((8 * s + t) ^ (g << 2))]);
            unsigned a2 = __float_as_uint(Cs[rowA * 64 + ((8 * s + t + 4) ^ (g << 2))]);
            unsigned a3 = __float_as_uint(Cs[rowB * 64 + ((8 * s + t + 4) ^ (g << 2))]);
            int kr0 = 8 * s + t, kr1 = 8 * s + t + 4;
#pragma unroll
            for (int nt = 0; nt < 32; nt++) {
                int c0 = (8 * nt + g) ^ (t << 3);
                unsigned b0 = __float_as_uint(KVs[kr0 * 256 + c0]);
                unsigned b1 = __float_as_uint(KVs[kr1 * 256 + c0]);
                mma_tf32(O[nt][0], O[nt][1], O[nt][2], O[nt][3], a0, a1, a2, a3, b0, b1);
            }
        }
    }

    // write partials
    const int r0 = m0 + rowA, r1 = m0 + rowB;
    if (t == 0) {
        g_ms[sp][r0] = m0r; g_ms[sp][r1] = m1r;
        g_ls[sp][r0] = l0r; g_ls[sp][r1] = l1r;
    }
#pragma unroll
    for (int nt = 0; nt < 32; nt++) {
        int col = 8 * nt + 2 * t;
        *(float2*)&g_Op[sp][r0][col] = make_float2(O[nt][0], O[nt][1]);
        *(float2*)&g_Op[sp][r1][col] = make_float2(O[nt][2], O[nt][3]);
    }
}

// ---------------- kernel 3: combine splits, normalize, ELU ----------------
__global__ __launch_bounds__(256) void combine_kernel(float* __restrict__ out) {
    const int i = blockIdx.x;
    const int d = threadIdx.x;
    float m0 = g_ms[0][i], m1 = g_ms[1][i], m2 = g_ms[2][i], m3 = g_ms[3][i];
    float mx = fmaxf(fmaxf(m0, m1), fmaxf(m2, m3));
    float e0 = __expf(m0 - mx), e1 = __expf(m1 - mx), e2 = __expf(m2 - mx), e3 = __expf(m3 - mx);
    float den = g_ls[0][i] * e0 + g_ls[1][i] * e1 + g_ls[2][i] * e2 + g_ls[3][i] * e3 + 1e-9f;
    float num = g_Op[0][i][d] * e0 + g_Op[1][i][d] * e1 + g_Op[2][i][d] * e2 + g_Op[3][i][d] * e3;
    float r = num / den;
    out[(size_t)i * DHEAD + d] = (r > 0.f) ? r : expm1f(r);
}

// ---------------- launch ----------------
extern "C" void kernel_launch(void* const* d_in, const int* in_sizes, int n_in,
                              void* d_out, int out_size) {
    (void)in_sizes; (void)n_in; (void)out_size;
    const float* feat = (const float*)d_in[0];
    const float* cnt = (const float*)d_in[1];
    const float* Wq = (const float*)d_in[2];
    const float* Wk = (const float*)d_in[3];
    const float* Wv = (const float*)d_in[4];

    proj_kernel<<<dim3(NTOK / 128, DHEAD / 128, 3), 256>>>(feat, Wq, Wk, Wv);

    const size_t smem = (size_t)(128 * 256 + 64 * 256 + 128 * 64) * sizeof(float);  // 229376 B
    cudaFuncSetAttribute(attn_kernel, cudaFuncAttributeMaxDynamicSharedMemorySize, (int)smem);
    attn_kernel<<<dim3(NTOK / BM, NSPLIT), 256, smem>>>(cnt);

    combine_kernel<<<NTOK, 256>>>((float*)d_out);
}

// round 4
// speedup vs baseline: 2.0220x; 2.0220x over previous
#include <cuda_runtime.h>
#include <cuda_fp16.h>
#include <cstdint>

#define NTOK 8192
#define DIN  512
#define DHEAD 256
#define NSPLIT 2
#define BM 128
#define BN 64
#define JBLOCKS (NTOK / NSPLIT / BN)   // 64 iterations per CTA

// ---------------- scratch ----------------
__device__ __half g_Qh[NTOK * DHEAD];        // fp16, pre-scaled by 1/16
__device__ __half g_Kh[NTOK * DHEAD];        // fp16
__device__ __half g_Vt[DHEAD * NTOK];        // V transposed [d][tok], fp16
__device__ float  g_Op[NSPLIT][NTOK][DHEAD];
__device__ float  g_ls[NSPLIT][NTOK];

// ---------------- helpers ----------------
__device__ __forceinline__ unsigned tf32_rna_u(float x) {
    unsigned u; asm("cvt.rna.tf32.f32 %0, %1;" : "=r"(u) : "f"(x)); return u;
}
__device__ __forceinline__ float tf32_rna(float x) { return __uint_as_float(tf32_rna_u(x)); }

// legacy tf32 mma (projection)
__device__ __forceinline__ void mma_tf32(float& c0, float& c1, float& c2, float& c3,
                                         unsigned a0, unsigned a1, unsigned a2, unsigned a3,
                                         unsigned b0, unsigned b1) {
    asm volatile(
        "mma.sync.aligned.m16n8k8.row.col.f32.tf32.tf32.f32 "
        "{%0,%1,%2,%3}, {%4,%5,%6,%7}, {%8,%9}, {%0,%1,%2,%3};"
        : "+f"(c0), "+f"(c1), "+f"(c2), "+f"(c3)
        : "r"(a0), "r"(a1), "r"(a2), "r"(a3), "r"(b0), "r"(b1));
}

// legacy fp16 mma m16n8k16, fp32 accumulate (attention)
__device__ __forceinline__ void mma_f16(float& c0, float& c1, float& c2, float& c3,
                                        unsigned a0, unsigned a1, unsigned a2, unsigned a3,
                                        unsigned b0, unsigned b1) {
    asm volatile(
        "mma.sync.aligned.m16n8k16.row.col.f32.f16.f16.f32 "
        "{%0,%1,%2,%3}, {%4,%5,%6,%7}, {%8,%9}, {%0,%1,%2,%3};"
        : "+f"(c0), "+f"(c1), "+f"(c2), "+f"(c3)
        : "r"(a0), "r"(a1), "r"(a2), "r"(a3), "r"(b0), "r"(b1));
}

// ---------------- kernel 1: QKV projection, tf32 x2, fp16 outputs ----------------
__global__ __launch_bounds__(256) void proj_kernel(const float* __restrict__ feat,
                                                   const float* __restrict__ Wq,
                                                   const float* __restrict__ Wk,
                                                   const float* __restrict__ Wv) {
    __shared__ float As[2][128][20];
    __shared__ float Bs[16][136];

    const int tid = threadIdx.x;
    const int w = tid >> 5, lane = tid & 31, g = lane >> 2, t = lane & 3;
    const int wm = w >> 1, wn = w & 1;
    const int m0 = blockIdx.x * 128;
    const int n0 = blockIdx.y * 128;
    const int mat = blockIdx.z;
    const float* __restrict__ W = (mat == 0) ? Wq : ((mat == 1) ? Wk : Wv);

    float acc[2][8][4];
#pragma unroll
    for (int mt = 0; mt < 2; mt++)
#pragma unroll
        for (int nt = 0; nt < 8; nt++)
#pragma unroll
            for (int j = 0; j < 4; j++) acc[mt][nt][j] = 0.f;

    for (int kb = 0; kb < DIN; kb += 16) {
#pragma unroll
        for (int i = 0; i < 2; i++) {
            int e = tid + 256 * i;
            int r = e >> 2, c = (e & 3) << 2;
            float4 v = *(const float4*)&feat[(size_t)(m0 + r) * DIN + kb + c];
            float h;
            h = tf32_rna(v.x); As[0][r][c + 0] = h; As[1][r][c + 0] = tf32_rna(v.x - h);
            h = tf32_rna(v.y); As[0][r][c + 1] = h; As[1][r][c + 1] = tf32_rna(v.y - h);
            h = tf32_rna(v.z); As[0][r][c + 2] = h; As[1][r][c + 2] = tf32_rna(v.z - h);
            h = tf32_rna(v.w); As[0][r][c + 3] = h; As[1][r][c + 3] = tf32_rna(v.w - h);
        }
#pragma unroll
        for (int i = 0; i < 2; i++) {
            int e = tid + 256 * i;
            int r = e >> 5, c = (e & 31) << 2;
            float4 v = *(const float4*)&W[(size_t)(kb + r) * DHEAD + n0 + c];
            Bs[r][c + 0] = tf32_rna(v.x);
            Bs[r][c + 1] = tf32_rna(v.y);
            Bs[r][c + 2] = tf32_rna(v.z);
            Bs[r][c + 3] = tf32_rna(v.w);
        }
        __syncthreads();

#pragma unroll
        for (int ks = 0; ks < 16; ks += 8) {
            unsigned b[8][2];
#pragma unroll
            for (int nt = 0; nt < 8; nt++) {
                int col = 64 * wn + 8 * nt + g;
                b[nt][0] = __float_as_uint(Bs[ks + t][col]);
                b[nt][1] = __float_as_uint(Bs[ks + t + 4][col]);
            }
#pragma unroll
            for (int sp2 = 0; sp2 < 2; sp2++) {
#pragma unroll
                for (int mt = 0; mt < 2; mt++) {
                    int r = 32 * wm + 16 * mt + g;
                    unsigned a0 = __float_as_uint(As[sp2][r][ks + t]);
                    unsigned a1 = __float_as_uint(As[sp2][r + 8][ks + t]);
                    unsigned a2 = __float_as_uint(As[sp2][r][ks + t + 4]);
                    unsigned a3 = __float_as_uint(As[sp2][r + 8][ks + t + 4]);
#pragma unroll
                    for (int nt = 0; nt < 8; nt++)
                        mma_tf32(acc[mt][nt][0], acc[mt][nt][1], acc[mt][nt][2], acc[mt][nt][3],
                                 a0, a1, a2, a3, b[nt][0], b[nt][1]);
                }
            }
        }
        __syncthreads();
    }

    const float scale = (mat == 0) ? 0.0625f : 1.0f;  // fold 1/sqrt(256) into Q
#pragma unroll
    for (int mt = 0; mt < 2; mt++) {
        int r = m0 + 32 * wm + 16 * mt + g;
#pragma unroll
        for (int nt = 0; nt < 8; nt++) {
            int col = n0 + 64 * wn + 8 * nt + 2 * t;
            __half h00 = __float2half_rn(acc[mt][nt][0] * scale);
            __half h01 = __float2half_rn(acc[mt][nt][1] * scale);
            __half h10 = __float2half_rn(acc[mt][nt][2] * scale);
            __half h11 = __float2half_rn(acc[mt][nt][3] * scale);
            if (mat == 2) {
                g_Vt[(size_t)col * NTOK + r] = h00;
                g_Vt[(size_t)(col + 1) * NTOK + r] = h01;
                g_Vt[(size_t)col * NTOK + r + 8] = h10;
                g_Vt[(size_t)(col + 1) * NTOK + r + 8] = h11;
            } else {
                __half* dst = (mat == 0) ? g_Qh : g_Kh;
                *(__half2*)&dst[(size_t)r * DHEAD + col] = __halves2half2(h00, h01);
                *(__half2*)&dst[(size_t)(r + 8) * DHEAD + col] = __halves2half2(h10, h11);
            }
        }
    }
}

// ---------------- kernel 2: fused attention, fp16 mma ----------------
// SMEM (bytes): Qs 64K | Ks 32K | Vs 32K | Cs 32K (fp32 cnt) | Ps 16K (fp16 P) | lred 1K
#define SMO_Q   0u
#define SMO_K   65536u
#define SMO_V   98304u
#define SMO_C   131072u
#define SMO_P   163840u
#define SMO_L   180224u
#define SMEM_DYN (180224u + 1024u)

__global__ __launch_bounds__(256, 1) void attn_kernel(const float* __restrict__ cnt) {
    extern __shared__ char sm[];
    __half* Qs = (__half*)(sm + SMO_Q);   // [128][256] swizzled (idx4 ^ ((row&7)<<2))
    __half* Ks = (__half*)(sm + SMO_K);   // [64][256]
    __half* Vs = (__half*)(sm + SMO_V);   // [256][64]  (V^T: row=d, col=key)
    float*  Cs = (float*)(sm + SMO_C);    // [128][64]
    __half* Ps = (__half*)(sm + SMO_P);   // [128][64]
    float*  Lr = (float*)(sm + SMO_L);    // [256]

    const int tid = threadIdx.x;
    const int w = tid >> 5, lane = tid & 31, g = lane >> 2, t = lane & 3;
    const int m0 = blockIdx.x * BM;
    const int sp = blockIdx.y;
    const int rowA = 16 * w + g, rowB = rowA + 8;

    // ---- load Q tile [128][256] fp16, swizzled ----
#pragma unroll
    for (int i = 0; i < 16; i++) {
        int e = tid + 256 * i;
        int r = e >> 5, blk = e & 31;                       // 32 uint4 per row
        int s4 = (4 * blk) ^ ((r & 7) << 2);                // idx4 swizzle
        *(uint4*)((char*)Qs + r * 512 + s4 * 4) =
            *(const uint4*)&g_Qh[(size_t)(m0 + r) * DHEAD + 8 * blk];
    }

    float O[32][4];
#pragma unroll
    for (int nt = 0; nt < 32; nt++)
#pragma unroll
        for (int j = 0; j < 4; j++) O[nt][j] = 0.f;
    float l0r = 0.f, l1r = 0.f;

    const int jb0 = sp * (NTOK / NSPLIT);
    for (int j = 0; j < JBLOCKS; j++) {
        const int jb = jb0 + j * BN;
        __syncthreads();  // previous iteration's smem reads complete

        // K block [64][256]
#pragma unroll
        for (int i = 0; i < 8; i++) {
            int e = tid + 256 * i;
            int r = e >> 5, blk = e & 31;
            int s4 = (4 * blk) ^ ((r & 7) << 2);
            *(uint4*)((char*)Ks + r * 512 + s4 * 4) =
                *(const uint4*)&g_Kh[(size_t)(jb + r) * DHEAD + 8 * blk];
        }
        // V^T block [256][64]
#pragma unroll
        for (int i = 0; i < 8; i++) {
            int e = tid + 256 * i;
            int d = e >> 3, blk = e & 7;                    // 8 uint4 per row
            int s4 = (4 * blk) ^ ((d & 7) << 2);
            *(uint4*)((char*)Vs + d * 128 + s4 * 4) =
                *(const uint4*)&g_Vt[(size_t)d * NTOK + jb + 8 * blk];
        }
        // counting tile [128][64] fp32
#pragma unroll
        for (int i = 0; i < 8; i++) {
            int e = tid + 256 * i;
            int r = e >> 4, blk = e & 15;                   // 16 float4 per row
            int s4 = (4 * blk) ^ ((r & 7) << 2);
            *(float4*)((char*)Cs + r * 256 + s4 * 4) =
                *(const float4*)&cnt[(size_t)(m0 + r) * NTOK + jb + 4 * blk];
        }
        __syncthreads();

        // ---- S = Q K^T : warp computes [16 x 64], k = 256 in 16 steps ----
        float S[8][4];
#pragma unroll
        for (int nt = 0; nt < 8; nt++)
#pragma unroll
            for (int q = 0; q < 4; q++) S[nt][q] = 0.f;

#pragma unroll 4
        for (int s = 0; s < 16; s++) {
            unsigned a0 = *(unsigned*)((char*)Qs + rowA * 512 + (((8 * s + t)     ^ (g << 2)) * 4));
            unsigned a1 = *(unsigned*)((char*)Qs + rowB * 512 + (((8 * s + t)     ^ (g << 2)) * 4));
            unsigned a2 = *(unsigned*)((char*)Qs + rowA * 512 + (((8 * s + t + 4) ^ (g << 2)) * 4));
            unsigned a3 = *(unsigned*)((char*)Qs + rowB * 512 + (((8 * s + t + 4) ^ (g << 2)) * 4));
#pragma unroll
            for (int nt = 0; nt < 8; nt++) {
                int n = 8 * nt + g;
                unsigned b0 = *(unsigned*)((char*)Ks + n * 512 + (((8 * s + t)     ^ (g << 2)) * 4));
                unsigned b1 = *(unsigned*)((char*)Ks + n * 512 + (((8 * s + t + 4) ^ (g << 2)) * 4));
                mma_f16(S[nt][0], S[nt][1], S[nt][2], S[nt][3], a0, a1, a2, a3, b0, b1);
            }
        }

        // ---- P = exp(S) * cnt; write fp16 P; accumulate row sums ----
        float s0 = 0.f, s1 = 0.f;
#pragma unroll
        for (int nt = 0; nt < 8; nt++) {
            int ci = (8 * nt + 2 * t) ^ (g << 2);
            float2 cA = *(float2*)((char*)Cs + rowA * 256 + ci * 4);
            float2 cB = *(float2*)((char*)Cs + rowB * 256 + ci * 4);
            float p0 = __expf(S[nt][0]) * cA.x;
            float p1 = __expf(S[nt][1]) * cA.y;
            float p2 = __expf(S[nt][2]) * cB.x;
            float p3 = __expf(S[nt][3]) * cB.y;
            s0 += p0 + p1;
            s1 += p2 + p3;
            int pi = (4 * nt + t) ^ (g << 2);
            *(__half2*)((char*)Ps + rowA * 128 + pi * 4) =
                __halves2half2(__float2half_rn(p0), __float2half_rn(p1));
            *(__half2*)((char*)Ps + rowB * 128 + pi * 4) =
                __halves2half2(__float2half_rn(p2), __float2half_rn(p3));
        }
        s0 += __shfl_xor_sync(0xffffffffu, s0, 1);
        s0 += __shfl_xor_sync(0xffffffffu, s0, 2);
        s1 += __shfl_xor_sync(0xffffffffu, s1, 1);
        s1 += __shfl_xor_sync(0xffffffffu, s1, 2);
        l0r += s0;
        l1r += s1;
        __syncthreads();  // P visible to all warps

        // ---- O += P @ V^T : warp [16 x 256], k = 64 in 4 steps ----
#pragma unroll
        for (int s = 0; s < 4; s++) {
            unsigned a0 = *(unsigned*)((char*)Ps + rowA * 128 + (((8 * s + t)     ^ (g << 2)) * 4));
            unsigned a1 = *(unsigned*)((char*)Ps + rowB * 128 + (((8 * s + t)     ^ (g << 2)) * 4));
            unsigned a2 = *(unsigned*)((char*)Ps + rowA * 128 + (((8 * s + t + 4) ^ (g << 2)) * 4));
            unsigned a3 = *(unsigned*)((char*)Ps + rowB * 128 + (((8 * s + t + 4) ^ (g << 2)) * 4));
#pragma unroll
            for (int nt = 0; nt < 32; nt++) {
                int d = 8 * nt + g;
                unsigned b0 = *(unsigned*)((char*)Vs + d * 128 + (((8 * s + t)     ^ (g << 2)) * 4));
                unsigned b1 = *(unsigned*)((char*)Vs + d * 128 + (((8 * s + t + 4) ^ (g << 2)) * 4));
                mma_f16(O[nt][0], O[nt][1], O[nt][2], O[nt][3], a0, a1, a2, a3, b0, b1);
            }
        }
    }

    // ---- writeout ----
    const int r0 = m0 + rowA, r1 = m0 + rowB;
    if (t == 0) {
        g_ls[sp][r0] = l0r;
        g_ls[sp][r1] = l1r;
    }
    (void)Lr;
#pragma unroll
    for (int nt = 0; nt < 32; nt++) {
        int col = 8 * nt + 2 * t;
        *(float2*)&g_Op[sp][r0][col] = make_float2(O[nt][0], O[nt][1]);
        *(float2*)&g_Op[sp][r1][col] = make_float2(O[nt][2], O[nt][3]);
    }
}

// ---------------- kernel 3: combine + ELU ----------------
__global__ __launch_bounds__(256) void combine_kernel(float* __restrict__ out) {
    const int i = blockIdx.x;
    const int d = threadIdx.x;
    float den = g_ls[0][i] + g_ls[1][i];
    float num = g_Op[0][i][d] + g_Op[1][i][d];
    float r = num / den;
    out[(size_t)i * DHEAD + d] = (r > 0.f) ? r : expm1f(r);
}

// ---------------- launch ----------------
extern "C" void kernel_launch(void* const* d_in, const int* in_sizes, int n_in,
                              void* d_out, int out_size) {
    (void)in_sizes; (void)n_in; (void)out_size;
    const float* feat = (const float*)d_in[0];
    const float* cnt = (const float*)d_in[1];
    const float* Wq = (const float*)d_in[2];
    const float* Wk = (const float*)d_in[3];
    const float* Wv = (const float*)d_in[4];

    proj_kernel<<<dim3(NTOK / 128, DHEAD / 128, 3), 256>>>(feat, Wq, Wk, Wv);

    cudaFuncSetAttribute(attn_kernel, cudaFuncAttributeMaxDynamicSharedMemorySize, (int)SMEM_DYN);
    attn_kernel<<<dim3(NTOK / BM, NSPLIT), 256, SMEM_DYN>>>(cnt);

    combine_kernel<<<NTOK, 256>>>((float*)d_out);
}

// round 5
// speedup vs baseline: 2.6907x; 1.3307x over previous
#include <cuda_runtime.h>
#include <cuda_fp16.h>
#include <cstdint>

#define NTOK 8192
#define DIN  512
#define DHEAD 256
#define NSPLIT 2
#define BM 128
#define BN 64
#define JBLOCKS (NTOK / NSPLIT / BN)   // 64

// ---------------- scratch ----------------
__device__ __half g_Qh[NTOK * DHEAD];        // fp16, pre-scaled by 1/16
__device__ __half g_Kh[NTOK * DHEAD];        // fp16
__device__ __half g_Vt[DHEAD * NTOK];        // V transposed [d][tok], fp16
__device__ float  g_Op[NSPLIT][NTOK][DHEAD];
__device__ float  g_ls[NSPLIT][NTOK];

// ---------------- helpers ----------------
__device__ __forceinline__ unsigned tf32_rna_u(float x) {
    unsigned u; asm("cvt.rna.tf32.f32 %0, %1;" : "=r"(u) : "f"(x)); return u;
}
__device__ __forceinline__ float tf32_rna(float x) { return __uint_as_float(tf32_rna_u(x)); }

__device__ __forceinline__ uint32_t smem_u32(const void* p) {
    uint32_t a;
    asm("{ .reg .u64 t; cvta.to.shared.u64 t, %1; cvt.u32.u64 %0, t; }" : "=r"(a) : "l"(p));
    return a;
}
__device__ __forceinline__ void cp16(uint32_t dst, const void* src) {
    asm volatile("cp.async.cg.shared.global [%0], [%1], 16;" :: "r"(dst), "l"(src));
}
#define CP_COMMIT() asm volatile("cp.async.commit_group;" ::: "memory")
#define CP_WAIT(n)  asm volatile("cp.async.wait_group %0;" :: "n"(n) : "memory")

__device__ __forceinline__ void mma_tf32(float& c0, float& c1, float& c2, float& c3,
                                         unsigned a0, unsigned a1, unsigned a2, unsigned a3,
                                         unsigned b0, unsigned b1) {
    asm volatile(
        "mma.sync.aligned.m16n8k8.row.col.f32.tf32.tf32.f32 "
        "{%0,%1,%2,%3}, {%4,%5,%6,%7}, {%8,%9}, {%0,%1,%2,%3};"
        : "+f"(c0), "+f"(c1), "+f"(c2), "+f"(c3)
        : "r"(a0), "r"(a1), "r"(a2), "r"(a3), "r"(b0), "r"(b1));
}
__device__ __forceinline__ void mma_f16(float& c0, float& c1, float& c2, float& c3,
                                        unsigned a0, unsigned a1, unsigned a2, unsigned a3,
                                        unsigned b0, unsigned b1) {
    asm volatile(
        "mma.sync.aligned.m16n8k16.row.col.f32.f16.f16.f32 "
        "{%0,%1,%2,%3}, {%4,%5,%6,%7}, {%8,%9}, {%0,%1,%2,%3};"
        : "+f"(c0), "+f"(c1), "+f"(c2), "+f"(c3)
        : "r"(a0), "r"(a1), "r"(a2), "r"(a3), "r"(b0), "r"(b1));
}

// ---------------- kernel 1: QKV projection, tf32 x2, fp16 outputs ----------------
__global__ __launch_bounds__(256) void proj_kernel(const float* __restrict__ feat,
                                                   const float* __restrict__ Wq,
                                                   const float* __restrict__ Wk,
                                                   const float* __restrict__ Wv) {
    __shared__ float As[2][128][20];
    __shared__ float Bs[16][136];

    const int tid = threadIdx.x;
    const int w = tid >> 5, lane = tid & 31, g = lane >> 2, t = lane & 3;
    const int wm = w >> 1, wn = w & 1;
    const int m0 = blockIdx.x * 128;
    const int n0 = blockIdx.y * 128;
    const int mat = blockIdx.z;
    const float* __restrict__ W = (mat == 0) ? Wq : ((mat == 1) ? Wk : Wv);

    float acc[2][8][4];
#pragma unroll
    for (int mt = 0; mt < 2; mt++)
#pragma unroll
        for (int nt = 0; nt < 8; nt++)
#pragma unroll
            for (int j = 0; j < 4; j++) acc[mt][nt][j] = 0.f;

    for (int kb = 0; kb < DIN; kb += 16) {
#pragma unroll
        for (int i = 0; i < 2; i++) {
            int e = tid + 256 * i;
            int r = e >> 2, c = (e & 3) << 2;
            float4 v = *(const float4*)&feat[(size_t)(m0 + r) * DIN + kb + c];
            float h;
            h = tf32_rna(v.x); As[0][r][c + 0] = h; As[1][r][c + 0] = tf32_rna(v.x - h);
            h = tf32_rna(v.y); As[0][r][c + 1] = h; As[1][r][c + 1] = tf32_rna(v.y - h);
            h = tf32_rna(v.z); As[0][r][c + 2] = h; As[1][r][c + 2] = tf32_rna(v.z - h);
            h = tf32_rna(v.w); As[0][r][c + 3] = h; As[1][r][c + 3] = tf32_rna(v.w - h);
        }
#pragma unroll
        for (int i = 0; i < 2; i++) {
            int e = tid + 256 * i;
            int r = e >> 5, c = (e & 31) << 2;
            float4 v = *(const float4*)&W[(size_t)(kb + r) * DHEAD + n0 + c];
            Bs[r][c + 0] = tf32_rna(v.x);
            Bs[r][c + 1] = tf32_rna(v.y);
            Bs[r][c + 2] = tf32_rna(v.z);
            Bs[r][c + 3] = tf32_rna(v.w);
        }
        __syncthreads();

#pragma unroll
        for (int ks = 0; ks < 16; ks += 8) {
            unsigned b[8][2];
#pragma unroll
            for (int nt = 0; nt < 8; nt++) {
                int col = 64 * wn + 8 * nt + g;
                b[nt][0] = __float_as_uint(Bs[ks + t][col]);
                b[nt][1] = __float_as_uint(Bs[ks + t + 4][col]);
            }
#pragma unroll
            for (int sp2 = 0; sp2 < 2; sp2++) {
#pragma unroll
                for (int mt = 0; mt < 2; mt++) {
                    int r = 32 * wm + 16 * mt + g;
                    unsigned a0 = __float_as_uint(As[sp2][r][ks + t]);
                    unsigned a1 = __float_as_uint(As[sp2][r + 8][ks + t]);
                    unsigned a2 = __float_as_uint(As[sp2][r][ks + t + 4]);
                    unsigned a3 = __float_as_uint(As[sp2][r + 8][ks + t + 4]);
#pragma unroll
                    for (int nt = 0; nt < 8; nt++)
                        mma_tf32(acc[mt][nt][0], acc[mt][nt][1], acc[mt][nt][2], acc[mt][nt][3],
                                 a0, a1, a2, a3, b[nt][0], b[nt][1]);
                }
            }
        }
        __syncthreads();
    }

    const float scale = (mat == 0) ? 0.0625f : 1.0f;  // fold 1/sqrt(256) into Q
#pragma unroll
    for (int mt = 0; mt < 2; mt++) {
        int r = m0 + 32 * wm + 16 * mt + g;
#pragma unroll
        for (int nt = 0; nt < 8; nt++) {
            int col = n0 + 64 * wn + 8 * nt + 2 * t;
            __half h00 = __float2half_rn(acc[mt][nt][0] * scale);
            __half h01 = __float2half_rn(acc[mt][nt][1] * scale);
            __half h10 = __float2half_rn(acc[mt][nt][2] * scale);
            __half h11 = __float2half_rn(acc[mt][nt][3] * scale);
            if (mat == 2) {
                g_Vt[(size_t)col * NTOK + r] = h00;
                g_Vt[(size_t)(col + 1) * NTOK + r] = h01;
                g_Vt[(size_t)col * NTOK + r + 8] = h10;
                g_Vt[(size_t)(col + 1) * NTOK + r + 8] = h11;
            } else {
                __half* dst = (mat == 0) ? g_Qh : g_Kh;
                *(__half2*)&dst[(size_t)r * DHEAD + col] = __halves2half2(h00, h01);
                *(__half2*)&dst[(size_t)(r + 8) * DHEAD + col] = __halves2half2(h10, h11);
            }
        }
    }
}

// ---------------- kernel 2: pipelined fp16 attention ----------------
// SMEM layout (bytes):
#define SMO_Q   0u        // [128][256] half, row stride 512, swizzled
#define SMO_K0  65536u    // [64][256] half
#define SMO_K1  98304u
#define SMO_V   131072u   // [256][64] half (V^T)
#define SMO_C   163840u   // [128][64] float (cnt)
#define SMO_P   196608u   // [128] rows x 144B (64 half + 8 pad), NOT swizzled
#define SMO_L   215040u   // 256 floats
#define SMEM_DYN (215040u + 1024u)

__global__ __launch_bounds__(256, 1) void attn_kernel(const float* __restrict__ cnt) {
    extern __shared__ char sm[];
    const uint32_t sb = smem_u32(sm);

    const int tid = threadIdx.x, w = tid >> 5, lane = tid & 31;
    const int g = lane >> 2, t = lane & 3;
    const int wm = w & 3, wh = w >> 2;     // 4 m-warps x 2 n/d-half warps
    const int m0 = blockIdx.x * BM;
    const int sp = blockIdx.y;
    const int jb0 = sp * (NTOK / NSPLIT);

    // ---- prologue: Q tile + K_0 via cp.async (group 0) ----
#pragma unroll
    for (int i = 0; i < 16; i++) {
        int e = tid + 256 * i;
        int r = e >> 5, blk = e & 31;
        uint32_t d = sb + SMO_Q + (uint32_t)r * 512u + (uint32_t)(((4 * blk) ^ ((r & 7) << 2)) << 2);
        cp16(d, &g_Qh[(size_t)(m0 + r) * DHEAD + 8 * blk]);
    }
#pragma unroll
    for (int i = 0; i < 8; i++) {
        int e = tid + 256 * i;
        int r = e >> 5, blk = e & 31;
        uint32_t d = sb + SMO_K0 + (uint32_t)r * 512u + (uint32_t)(((4 * blk) ^ ((r & 7) << 2)) << 2);
        cp16(d, &g_Kh[(size_t)(jb0 + r) * DHEAD + 8 * blk]);
    }
    CP_COMMIT();

    float O[2][16][4];
#pragma unroll
    for (int mt = 0; mt < 2; mt++)
#pragma unroll
        for (int nt = 0; nt < 16; nt++)
#pragma unroll
            for (int q = 0; q < 4; q++) O[mt][nt][q] = 0.f;
    float lA[2] = {0.f, 0.f}, lB[2] = {0.f, 0.f};

    const int rA0 = 32 * wm + g, rB0 = rA0 + 8;   // mt=0 rows; mt=1 adds 16

    for (int j = 0; j < JBLOCKS; j++) {
        const int jb = jb0 + j * BN;
        __syncthreads();   // prev AV done with V/P; K[(j+1)&1] and C free

        // ---- issue V_j + C_j (one group) ----
#pragma unroll
        for (int i = 0; i < 8; i++) {
            int e = tid + 256 * i;
            int dd = e >> 3, blk = e & 7;
            uint32_t d = sb + SMO_V + (uint32_t)dd * 128u + (uint32_t)(((4 * blk) ^ ((dd & 7) << 2)) << 2);
            cp16(d, &g_Vt[(size_t)dd * NTOK + jb + 8 * blk]);
        }
#pragma unroll
        for (int i = 0; i < 8; i++) {
            int e = tid + 256 * i;
            int r = e >> 4, blk = e & 15;
            uint32_t d = sb + SMO_C + (uint32_t)r * 256u + (uint32_t)(((4 * blk) ^ ((r & 7) << 2)) << 2);
            cp16(d, &cnt[(size_t)(m0 + r) * NTOK + jb + 4 * blk]);
        }
        CP_COMMIT();

        // ---- issue K_{j+1} (own group; empty group on last iter) ----
        if (j + 1 < JBLOCKS) {
            uint32_t kb = ((j + 1) & 1) ? SMO_K1 : SMO_K0;
#pragma unroll
            for (int i = 0; i < 8; i++) {
                int e = tid + 256 * i;
                int r = e >> 5, blk = e & 31;
                uint32_t d = sb + kb + (uint32_t)r * 512u + (uint32_t)(((4 * blk) ^ ((r & 7) << 2)) << 2);
                cp16(d, &g_Kh[(size_t)(jb + BN + r) * DHEAD + 8 * blk]);
            }
        }
        CP_COMMIT();

        CP_WAIT(2);        // K_j (and Q on j=0) complete
        __syncthreads();

        // ---- QK_j : warp computes S[32 rows x 32 cols], k = 256 ----
        const char* Ks = sm + ((j & 1) ? SMO_K1 : SMO_K0);
        const char* Qs = sm + SMO_Q;
        float S[2][4][4];
#pragma unroll
        for (int mt = 0; mt < 2; mt++)
#pragma unroll
            for (int nt = 0; nt < 4; nt++)
#pragma unroll
                for (int q = 0; q < 4; q++) S[mt][nt][q] = 0.f;

#pragma unroll 4
        for (int s = 0; s < 16; s++) {
            const int i0 = ((8 * s + t) ^ (g << 2)) << 2;
            const int i1 = ((8 * s + t + 4) ^ (g << 2)) << 2;
            unsigned b[4][2];
#pragma unroll
            for (int nt = 0; nt < 4; nt++) {
                int n = 32 * wh + 8 * nt + g;
                b[nt][0] = *(const unsigned*)(Ks + n * 512 + i0);
                b[nt][1] = *(const unsigned*)(Ks + n * 512 + i1);
            }
#pragma unroll
            for (int mt = 0; mt < 2; mt++) {
                int rA = (rA0 + 16 * mt) * 512, rB = (rB0 + 16 * mt) * 512;
                unsigned a0 = *(const unsigned*)(Qs + rA + i0);
                unsigned a1 = *(const unsigned*)(Qs + rB + i0);
                unsigned a2 = *(const unsigned*)(Qs + rA + i1);
                unsigned a3 = *(const unsigned*)(Qs + rB + i1);
#pragma unroll
                for (int nt = 0; nt < 4; nt++)
                    mma_f16(S[mt][nt][0], S[mt][nt][1], S[mt][nt][2], S[mt][nt][3],
                            a0, a1, a2, a3, b[nt][0], b[nt][1]);
            }
        }

        CP_WAIT(1);        // V_j + C_j complete (K_{j+1} may still fly)
        __syncthreads();

        // ---- epilogue: P = exp(S) * cnt -> Ps (fp16), accumulate l ----
        const char* Cs = sm + SMO_C;
        char* Ps = sm + SMO_P;
#pragma unroll
        for (int mt = 0; mt < 2; mt++) {
            int rA = rA0 + 16 * mt, rB = rB0 + 16 * mt;
            float sA = 0.f, sB = 0.f;
#pragma unroll
            for (int nt = 0; nt < 4; nt++) {
                int ci = ((32 * wh + 8 * nt + 2 * t) ^ (g << 2)) << 2;
                float2 cA = *(const float2*)(Cs + rA * 256 + ci);
                float2 cB = *(const float2*)(Cs + rB * 256 + ci);
                float p0 = __expf(S[mt][nt][0]) * cA.x;
                float p1 = __expf(S[mt][nt][1]) * cA.y;
                float p2 = __expf(S[mt][nt][2]) * cB.x;
                float p3 = __expf(S[mt][nt][3]) * cB.y;
                sA += p0 + p1;
                sB += p2 + p3;
                int q = (16 * wh + 4 * nt + t) << 2;
                *(__half2*)(Ps + rA * 144 + q) = __halves2half2(__float2half_rn(p0), __float2half_rn(p1));
                *(__half2*)(Ps + rB * 144 + q) = __halves2half2(__float2half_rn(p2), __float2half_rn(p3));
            }
            sA += __shfl_xor_sync(0xffffffffu, sA, 1);
            sA += __shfl_xor_sync(0xffffffffu, sA, 2);
            sB += __shfl_xor_sync(0xffffffffu, sB, 1);
            sB += __shfl_xor_sync(0xffffffffu, sB, 2);
            lA[mt] += sA;
            lB[mt] += sB;
        }
        __syncthreads();   // P visible to all warps

        // ---- AV_j : O[32 rows x 128 cols(d-half)] += P @ V^T, k = 64 ----
        const char* Vs = sm + SMO_V;
        const char* Psr = sm + SMO_P;
#pragma unroll
        for (int s = 0; s < 4; s++) {
            const int i0 = ((8 * s + t) ^ (g << 2)) << 2;
            const int i1 = ((8 * s + t + 4) ^ (g << 2)) << 2;
            const int p0i = (8 * s + t) << 2;
            const int p1i = (8 * s + t + 4) << 2;
            unsigned bv[16][2];
#pragma unroll
            for (int nt = 0; nt < 16; nt++) {
                int d = 128 * wh + 8 * nt + g;
                bv[nt][0] = *(const unsigned*)(Vs + d * 128 + i0);
                bv[nt][1] = *(const unsigned*)(Vs + d * 128 + i1);
            }
#pragma unroll
            for (int mt = 0; mt < 2; mt++) {
                int rA = (rA0 + 16 * mt) * 144, rB = (rB0 + 16 * mt) * 144;
                unsigned a0 = *(const unsigned*)(Psr + rA + p0i);
                unsigned a1 = *(const unsigned*)(Psr + rB + p0i);
                unsigned a2 = *(const unsigned*)(Psr + rA + p1i);
                unsigned a3 = *(const unsigned*)(Psr + rB + p1i);
#pragma unroll
                for (int nt = 0; nt < 16; nt++)
                    mma_f16(O[mt][nt][0], O[mt][nt][1], O[mt][nt][2], O[mt][nt][3],
                            a0, a1, a2, a3, bv[nt][0], bv[nt][1]);
            }
        }
    }

    // ---- O writeout ----
#pragma unroll
    for (int mt = 0; mt < 2; mt++) {
        int rA = m0 + rA0 + 16 * mt, rB = m0 + rB0 + 16 * mt;
#pragma unroll
        for (int nt = 0; nt < 16; nt++) {
            int col = 128 * wh + 8 * nt + 2 * t;
            *(float2*)&g_Op[sp][rA][col] = make_float2(O[mt][nt][0], O[mt][nt][1]);
            *(float2*)&g_Op[sp][rB][col] = make_float2(O[mt][nt][2], O[mt][nt][3]);
        }
    }

    // ---- l reduce across the two wh warps ----
    float* Lr = (float*)(sm + SMO_L);
    if (t == 0) {
#pragma unroll
        for (int mt = 0; mt < 2; mt++) {
            Lr[wh * 128 + rA0 + 16 * mt] = lA[mt];
            Lr[wh * 128 + rB0 + 16 * mt] = lB[mt];
        }
    }
    __syncthreads();
    if (tid < 128) g_ls[sp][m0 + tid] = Lr[tid] + Lr[128 + tid];
}

// ---------------- kernel 3: combine + ELU ----------------
__global__ __launch_bounds__(256) void combine_kernel(float* __restrict__ out) {
    const int i = blockIdx.x;
    const int d = threadIdx.x;
    float den = g_ls[0][i] + g_ls[1][i];
    float num = g_Op[0][i][d] + g_Op[1][i][d];
    float r = num / den;
    out[(size_t)i * DHEAD + d] = (r > 0.f) ? r : expm1f(r);
}

// ---------------- launch ----------------
extern "C" void kernel_launch(void* const* d_in, const int* in_sizes, int n_in,
                              void* d_out, int out_size) {
    (void)in_sizes; (void)n_in; (void)out_size;
    const float* feat = (const float*)d_in[0];
    const float* cnt = (const float*)d_in[1];
    const float* Wq = (const float*)d_in[2];
    const float* Wk = (const float*)d_in[3];
    const float* Wv = (const float*)d_in[4];

    proj_kernel<<<dim3(NTOK / 128, DHEAD / 128, 3), 256>>>(feat, Wq, Wk, Wv);

    cudaFuncSetAttribute(attn_kernel, cudaFuncAttributeMaxDynamicSharedMemorySize, (int)SMEM_DYN);
    attn_kernel<<<dim3(NTOK / BM, NSPLIT), 256, SMEM_DYN>>>(cnt);

    combine_kernel<<<NTOK, 256>>>((float*)d_out);
}